// round 16
// baseline (speedup 1.0000x reference)
#include <cuda_runtime.h>
#include <cuda_fp16.h>
#include <math.h>

// ---------------- problem constants ----------------
#define D    768
#define DH   3072
#define BB   8
#define TT   8
#define NT   197
#define BT   64
#define NHD  12
#define HD   64
#define ST   1569
#define MXT  (BT*NT)        // 12608
#define MY   (BB*ST)        // 12552
#define YSZ  (MY*D)
#define LMSZ (BT*NT*NT)

#define GS3  3
#define STGB 18432                 // 128 rows x 144 B per stage
#define SMEM_H (2*GS3*STGB)        // 110592 B -> 2 CTAs/SM

// ---------------- scratch ----------------
__device__ __half g_xth [MXT*D];
__device__ __half g_xnh [MXT*D];
__device__ __half g_qmkh[MXT*2*D];
__device__ float  g_bqk [2*D];
__device__ __half g_qkvh[MXT*3*D];
__device__ __half g_oh  [MXT*D];
__device__ __half g_oph [MXT*D];
__device__ __half g_xn2h[MY*D];
__device__ __half g_hh  [MY*DH];
__device__ __half g_wqkh [2*D*D];
__device__ __half g_wqkvh[3*D*D];
__device__ __half g_wprh [D*D];
__device__ __half g_wf1h [DH*D];
__device__ __half g_wf2h [D*DH];

// ---------------- helpers ----------------
__device__ __forceinline__ void mma16h(float* c, const unsigned* a, const unsigned* b) {
    asm volatile(
        "mma.sync.aligned.m16n8k16.row.col.f32.f16.f16.f32 "
        "{%0,%1,%2,%3}, {%4,%5,%6,%7}, {%8,%9}, {%0,%1,%2,%3};"
        : "+f"(c[0]), "+f"(c[1]), "+f"(c[2]), "+f"(c[3])
        : "r"(a[0]), "r"(a[1]), "r"(a[2]), "r"(a[3]), "r"(b[0]), "r"(b[1]));
}

__device__ __forceinline__ void ldsm_x4(unsigned* r, unsigned addr) {
    asm volatile("ldmatrix.sync.aligned.m8n8.x4.shared.b16 {%0,%1,%2,%3}, [%4];"
        : "=r"(r[0]), "=r"(r[1]), "=r"(r[2]), "=r"(r[3]) : "r"(addr));
}

__device__ __forceinline__ void cpa16(unsigned dst, const void* src, bool p) {
    asm volatile("cp.async.cg.shared.global [%0], [%1], 16, %2;"
        :: "r"(dst), "l"(src), "r"(p ? 16 : 0));
}
#define CP_COMMIT asm volatile("cp.async.commit_group;")
template<int N> __device__ __forceinline__ void cp_wait() {
    asm volatile("cp.async.wait_group %0;" :: "n"(N));
}

// ---------------- merged weight prep (fp16) ----------------
__global__ void round_weights(const float* __restrict__ Wqkv, const float* __restrict__ Wpr,
                              const float* __restrict__ Wf1, const float* __restrict__ Wf2,
                              const float* __restrict__ Wmq, const float* __restrict__ Wmk,
                              const float* __restrict__ bmq, const float* __restrict__ bmk) {
    const int DD = D * D;
    int i = blockIdx.x * blockDim.x + threadIdx.x;
    if (i < 3 * DD)        g_wqkvh[i]          = __float2half(Wqkv[i]);
    else if (i < 4 * DD)   g_wprh[i - 3 * DD]  = __float2half(Wpr[i - 3 * DD]);
    else if (i < 8 * DD)   g_wf1h[i - 4 * DD]  = __float2half(Wf1[i - 4 * DD]);
    else if (i < 12 * DD)  g_wf2h[i - 8 * DD]  = __float2half(Wf2[i - 8 * DD]);
    else if (i < 13 * DD)  g_wqkh[i - 12 * DD] = __float2half(Wmq[i - 12 * DD]);
    else if (i < 14 * DD)  g_wqkh[DD + i - 13 * DD] = __float2half(Wmk[i - 13 * DD]);
    if (i < D) g_bqk[i] = bmq[i];
    else if (i < 2 * D) g_bqk[i] = bmk[i - D];
}

// ---------------- fused gather + LayerNorm1 -> xth, xnh (fp16) ----------------
__global__ void gather_ln(const float* __restrict__ x, const float* __restrict__ g,
                          const float* __restrict__ be,
                          __half* __restrict__ xth, __half* __restrict__ xnh) {
    int row = blockIdx.x;
    int tid = threadIdx.x;
    int n  = row % NT;
    int bt = row / NT;
    int b = bt / TT, t = bt % TT;
    int src = (n == 0) ? (b * ST) : (b * ST + 1 + (n - 1) * TT + t);
    const float* xr = x + (long)src * D;
    float v0 = xr[tid], v1 = xr[tid + 256], v2 = xr[tid + 512];
    __half* xtr = xth + (long)row * D;
    xtr[tid] = __float2half(v0); xtr[tid + 256] = __float2half(v1); xtr[tid + 512] = __float2half(v2);

    __shared__ float red[256];
    red[tid] = v0 + v1 + v2;
    __syncthreads();
    for (int o = 128; o > 0; o >>= 1) { if (tid < o) red[tid] += red[tid + o]; __syncthreads(); }
    float mean = red[0] * (1.0f / D);
    __syncthreads();
    float d0 = v0 - mean, d1 = v1 - mean, d2 = v2 - mean;
    red[tid] = d0*d0 + d1*d1 + d2*d2;
    __syncthreads();
    for (int o = 128; o > 0; o >>= 1) { if (tid < o) red[tid] += red[tid + o]; __syncthreads(); }
    float rs = rsqrtf(red[0] * (1.0f / D) + 1e-5f);
    __half* yr = xnh + (long)row * D;
    yr[tid]       = __float2half(d0 * rs * g[tid]       + be[tid]);
    yr[tid + 256] = __float2half(d1 * rs * g[tid + 256] + be[tid + 256]);
    yr[tid + 512] = __float2half(d2 * rs * g[tid + 512] + be[tid + 512]);
}

// ---------------- fp16 GEMM: m16n8k16, K-tile=64 halves, GS=3, optional batch ----------------
// A: MxK f16 (lda), B: NxK f16 (ldb). Batch via blockIdx.z when sC != 0.
// ep low 3 bits: 0=+bias 1=+bias,gelu 2=+bias,+Res 3=sigmoid w/ forced [0,0]=100
// bit4 (16): out fp16 to Ch (else fp32 to C). K % 64 == 0 required.
__global__ __launch_bounds__(256, 2) void gemm_h16(
    const __half* __restrict__ A, const __half* __restrict__ B,
    const float* __restrict__ bias, const float* __restrict__ Res,
    float* __restrict__ C, __half* __restrict__ Ch,
    int M, int N, int K, int lda, int ldb, int ldc,
    long long sAo, long long sBo, long long sC, int ep)
{
    extern __shared__ __align__(16) float dyn[];

    int tid  = threadIdx.x;
    int warp = tid >> 5, lane = tid & 31;
    int g = lane >> 2, tig = lane & 3;
    int wm = warp >> 2;
    int wn = warp & 3;
    int m0 = blockIdx.y * 128, n0 = blockIdx.x * 128;

    const __half* Ab = A;
    const __half* Bb = B;
    float* Cb = C;
    __half* Chb = Ch;
    if (sC) {
        long long z = blockIdx.z;
        Ab += z * sAo;
        Bb += z * sBo;
        if (C)  Cb  += z * sC;
        if (Ch) Chb += z * sC;
    }

    // loaders: 128 rows x 128B per tile; 2 threads/row, each 64B (4 x cpa16)
    int lrow = tid >> 1;
    int hof  = (tid & 1) * 32;       // halves offset in row
    bool aok = (m0 + lrow) < M;
    bool bok = (n0 + lrow) < N;
    const __half* Ap = Ab + (long long)(m0 + lrow) * lda + hof;
    const __half* Bp = Bb + (long long)(n0 + lrow) * ldb + hof;

    unsigned smB = (unsigned)__cvta_generic_to_shared(dyn);
    unsigned aSt = smB + lrow * 144 + hof * 2;
    unsigned bSt = smB + GS3 * STGB + lrow * 144 + hof * 2;

    int arow = lane & 15;
    int acolB = (lane >> 4) * 16;
    int brow = (lane & 7) + ((lane & 16) >> 1);
    int bcolB = ((lane >> 3) & 1) * 16;
    unsigned aAddr = smB + (wm * 64 + arow) * 144 + acolB;
    unsigned bAddr = smB + GS3 * STGB + (wn * 32 + brow) * 144 + bcolB;

    float acc[4][4][4];
    #pragma unroll
    for (int mt = 0; mt < 4; mt++)
        #pragma unroll
        for (int nt = 0; nt < 4; nt++)
            #pragma unroll
            for (int i = 0; i < 4; i++) acc[mt][nt][i] = 0.f;

    int nkt = K >> 6;     // 64 halves per tile

#define LOAD_TILE64(t, s) do { \
        const __half* As_ = Ap + (t) * 64; \
        const __half* Bs_ = Bp + (t) * 64; \
        unsigned ad_ = aSt + (s) * STGB; \
        unsigned bd_ = bSt + (s) * STGB; \
        cpa16(ad_,      As_,      aok); \
        cpa16(ad_ + 16, As_ + 8,  aok); \
        cpa16(ad_ + 32, As_ + 16, aok); \
        cpa16(ad_ + 48, As_ + 24, aok); \
        cpa16(bd_,      Bs_,      bok); \
        cpa16(bd_ + 16, Bs_ + 8,  bok); \
        cpa16(bd_ + 32, Bs_ + 16, bok); \
        cpa16(bd_ + 48, Bs_ + 24, bok); \
        CP_COMMIT; \
    } while (0)

    // prologue: tiles 0,1
    LOAD_TILE64(0, 0);
    if (nkt > 1) LOAD_TILE64(1, 1); else CP_COMMIT;

#define LOADFRAGH(aB, bB, kko) do { \
        ldsm_x4(fa[0], (aB) + 0 * 2304 + (kko)); \
        ldsm_x4(fa[1], (aB) + 1 * 2304 + (kko)); \
        ldsm_x4(fa[2], (aB) + 2 * 2304 + (kko)); \
        ldsm_x4(fa[3], (aB) + 3 * 2304 + (kko)); \
        ldsm_x4(fb2[0], (bB) + 0 * 2304 + (kko)); \
        ldsm_x4(fb2[1], (bB) + 1 * 2304 + (kko)); \
    } while (0)
#define MMAH_ALL do { \
        _Pragma("unroll") \
        for (int mt = 0; mt < 4; mt++) \
            _Pragma("unroll") \
            for (int nt = 0; nt < 4; nt++) { \
                unsigned bb[2] = { fb2[nt >> 1][(nt & 1) * 2], fb2[nt >> 1][(nt & 1) * 2 + 1] }; \
                mma16h(acc[mt][nt], fa[mt], bb); \
            } \
    } while (0)

    int cur = 0, ps = 2;
    for (int t = 0; t < nkt; t++) {
        cp_wait<1>();
        __syncthreads();

        {   // prefetch tile t+2 into stage ps (freed at iter t-1)
            int pf = t + 2;
            if (pf < nkt) LOAD_TILE64(pf, ps);
            else CP_COMMIT;
        }

        unsigned aB = aAddr + cur * STGB;
        unsigned bB = bAddr + cur * STGB;
        unsigned fa[4][4], fb2[2][4];
        LOADFRAGH(aB, bB, 0);
        MMAH_ALL;
        LOADFRAGH(aB, bB, 32);
        MMAH_ALL;
        LOADFRAGH(aB, bB, 64);
        MMAH_ALL;
        LOADFRAGH(aB, bB, 96);
        MMAH_ALL;

        if (++cur == GS3) cur = 0;
        if (++ps == GS3) ps = 0;
    }
#undef LOADFRAGH
#undef MMAH_ALL
#undef LOAD_TILE64

    int base_ep = ep & 7;
    bool outh = (ep & 16) != 0;
    bool v2ok = (ldc & 1) == 0;

    #pragma unroll
    for (int mt = 0; mt < 4; mt++) {
        int r0 = m0 + wm * 64 + mt * 16 + g;
        #pragma unroll
        for (int nt = 0; nt < 4; nt++) {
            int c0 = n0 + wn * 32 + nt * 8 + tig * 2;
            #pragma unroll
            for (int i = 0; i < 2; i++) {
                int rr = r0 + i * 8;
                if (rr >= M) continue;
                float v[2];
                #pragma unroll
                for (int j = 0; j < 2; j++) {
                    int cc = c0 + j;
                    float t = acc[mt][nt][i * 2 + j];
                    if (base_ep == 3) {
                        if (rr == 0 && cc == 0) t = 100.0f;
                        t = 1.0f / (1.0f + expf(-t));
                    } else {
                        if (bias) t += bias[cc];
                        if (base_ep == 1) t = 0.5f * t * (1.0f + erff(t * 0.7071067811865476f));
                        else if (base_ep == 2) t += Res[(long long)rr * ldc + cc];
                    }
                    v[j] = t;
                }
                if (outh) {
                    __half2 p;
                    p.x = __float2half(v[0]);
                    p.y = __float2half(v[1]);
                    *(__half2*)&Chb[(long long)rr * ldc + c0] = p;
                } else if (v2ok && c0 + 1 < N) {
                    *(float2*)&Cb[(long long)rr * ldc + c0] = make_float2(v[0], v[1]);
                } else {
                    if (c0 < N)     Cb[(long long)rr * ldc + c0] = v[0];
                    if (c0 + 1 < N) Cb[(long long)rr * ldc + c0 + 1] = v[1];
                }
            }
        }
    }
}

// ---------------- fused attention, fp16 MMAs + fp16 score buffer (2 CTA/SM) ----------------
#define SKH 72
#define SPH 210
#define OQ  0
#define OK_ (OQ + 64*SKH)
#define OV  (OK_ + 200*SKH)
#define OP_ (OV + 64*SPH)
#define SM_ATT ((OP_ + 64*SPH)*2)

__global__ __launch_bounds__(256, 2) void fused_attn(
    const __half* __restrict__ qkv, const float* __restrict__ lm, __half* __restrict__ o)
{
    extern __shared__ char smc[];
    __half* Qs = (__half*)smc + OQ;
    __half* Ks = (__half*)smc + OK_;
    __half* Vt = (__half*)smc + OV;
    __half* Ph = (__half*)smc + OP_;

    int tid = threadIdx.x;
    int w = tid >> 5, lane = tid & 31;
    int g = lane >> 2, tig = lane & 3;
    int qi = blockIdx.x, h = blockIdx.y, bt = blockIdx.z;
    int q0 = qi * 64;
    const __half* base = qkv + (long)bt * NT * 3 * D + h * HD;

    {
        int r = tid >> 2;
        int c = (tid & 3) * 16;
        int q = q0 + r;
        if (q < NT) {
            const uint4* p = (const uint4*)(base + (long)q * 3 * D + c);
            *(uint4*)&Qs[r * SKH + c]     = p[0];
            *(uint4*)&Qs[r * SKH + c + 8] = p[1];
        } else {
            #pragma unroll
            for (int j = 0; j < 16; j++) Qs[r * SKH + c + j] = __float2half(0.f);
        }
    }
    {
        int c = (tid & 3) * 16;
        for (int r = tid >> 2; r < NT; r += 64) {
            const uint4* p = (const uint4*)(base + (long)r * 3 * D + D + c);
            *(uint4*)&Ks[r * SKH + c]     = p[0];
            *(uint4*)&Ks[r * SKH + c + 8] = p[1];
        }
        for (int i = tid; i < 3 * 64; i += 256)
            Ks[(197 + i / 64) * SKH + (i % 64)] = __float2half(0.f);
    }
    {
        int c4 = (tid & 15) * 4;
        for (int m = tid >> 4; m < NT; m += 16) {
            const __half* vp = base + (long)m * 3 * D + 2 * D + c4;
            __half2 va = *(const __half2*)vp;
            __half2 vb = *(const __half2*)(vp + 2);
            Vt[(c4 + 0) * SPH + m] = va.x;
            Vt[(c4 + 1) * SPH + m] = va.y;
            Vt[(c4 + 2) * SPH + m] = vb.x;
            Vt[(c4 + 3) * SPH + m] = vb.y;
        }
        for (int i = tid; i < 64 * 13; i += 256)
            Vt[(i / 13) * SPH + 197 + (i % 13)] = __float2half(0.f);
    }
    __syncthreads();

    {
        int wm = w & 3;
        int wn = w >> 2;
        int nt0 = wn ? 13 : 0, nt1 = wn ? 25 : 13;
        int ra0 = (wm * 16 + g) * SKH;
        for (int nt = nt0; nt < nt1; nt++) {
            float c[4] = {0.f, 0.f, 0.f, 0.f};
            int rb0 = (nt * 8 + g) * SKH;
            #pragma unroll
            for (int kk = 0; kk < 64; kk += 16) {
                unsigned a[4], b[2];
                a[0] = *(const unsigned*)&Qs[ra0 + kk + 2 * tig];
                a[1] = *(const unsigned*)&Qs[ra0 + 8 * SKH + kk + 2 * tig];
                a[2] = *(const unsigned*)&Qs[ra0 + kk + 2 * tig + 8];
                a[3] = *(const unsigned*)&Qs[ra0 + 8 * SKH + kk + 2 * tig + 8];
                b[0] = *(const unsigned*)&Ks[rb0 + kk + 2 * tig];
                b[1] = *(const unsigned*)&Ks[rb0 + kk + 2 * tig + 8];
                mma16h(c, a, b);
            }
            int rm = wm * 16 + g, cn = nt * 8 + tig * 2;
            __half2 p0, p1;
            p0.x = __float2half(c[0]); p0.y = __float2half(c[1]);
            p1.x = __float2half(c[2]); p1.y = __float2half(c[3]);
            *(__half2*)&Ph[rm * SPH + cn]       = p0;
            *(__half2*)&Ph[(rm + 8) * SPH + cn] = p1;
        }
    }
    __syncthreads();

    {
        for (int rr = 0; rr < 8; rr++) {
            int r = (w << 3) + rr;
            int q = q0 + r;
            if (q < NT) {
                const float* lmr = lm + ((long)bt * NT + q) * NT;
                float mx = -1e30f;
                for (int k = lane; k < NT; k += 32) mx = fmaxf(mx, __half2float(Ph[r * SPH + k]));
                #pragma unroll
                for (int s = 16; s > 0; s >>= 1) mx = fmaxf(mx, __shfl_xor_sync(0xffffffffu, mx, s));
                float sum = 0.f;
                float ev[7];
                int cnt = 0;
                for (int k = lane; k < NT; k += 32) {
                    float e = expf(0.125f * (__half2float(Ph[r * SPH + k]) - mx));
                    ev[cnt++] = e;
                    sum += e;
                }
                #pragma unroll
                for (int s = 16; s > 0; s >>= 1) sum += __shfl_xor_sync(0xffffffffu, sum, s);
                float inv = 1.0f / sum;
                cnt = 0;
                for (int k = lane; k < SPH; k += 32) {
                    float p = (k < NT) ? (ev[cnt++] * inv * lmr[k]) : 0.f;
                    Ph[r * SPH + k] = __float2half(p);
                }
            } else {
                for (int k = lane; k < SPH; k += 32) Ph[r * SPH + k] = __float2half(0.f);
            }
        }
    }
    __syncthreads();

    {
        int wmA = w >> 1;
        int wnA = w & 1;
        float acc[4][4];
        #pragma unroll
        for (int nt = 0; nt < 4; nt++)
            #pragma unroll
            for (int i = 0; i < 4; i++) acc[nt][i] = 0.f;

        int ra0 = (wmA * 16 + g) * SPH;
        for (int kk = 0; kk < 208; kk += 16) {
            unsigned a[4], b[4][2];
            a[0] = *(const unsigned*)&Ph[ra0 + kk + 2 * tig];
            a[1] = *(const unsigned*)&Ph[ra0 + 8 * SPH + kk + 2 * tig];
            a[2] = *(const unsigned*)&Ph[ra0 + kk + 2 * tig + 8];
            a[3] = *(const unsigned*)&Ph[ra0 + 8 * SPH + kk + 2 * tig + 8];
            #pragma unroll
            for (int nt = 0; nt < 4; nt++) {
                int rb0 = (wnA * 32 + nt * 8 + g) * SPH;
                b[nt][0] = *(const unsigned*)&Vt[rb0 + kk + 2 * tig];
                b[nt][1] = *(const unsigned*)&Vt[rb0 + kk + 2 * tig + 8];
            }
            #pragma unroll
            for (int nt = 0; nt < 4; nt++) mma16h(acc[nt], a, b[nt]);
        }

        #pragma unroll
        for (int nt = 0; nt < 4; nt++) {
            int cn = wnA * 32 + nt * 8 + tig * 2;
            #pragma unroll
            for (int i = 0; i < 2; i++) {
                int q = q0 + wmA * 16 + g + i * 8;
                if (q >= NT) continue;
                __half* op = o + ((long)bt * NT + q) * D + h * HD + cn;
                __half2 p;
                p.x = __float2half(acc[nt][i * 2]);
                p.y = __float2half(acc[nt][i * 2 + 1]);
                *(__half2*)op = p;
            }
        }
    }
}

// ---------------- fused scatter(+residual, fp16 op) + LayerNorm2 -> y (fp32), xn2h ----------------
__global__ void scatter_ln(const float* __restrict__ x, const __half* __restrict__ op,
                           const float* __restrict__ g, const float* __restrict__ be,
                           float* __restrict__ y, __half* __restrict__ xn2h) {
    int row = blockIdx.x;
    int tid = threadIdx.x;
    int p = row % ST;
    int b = row / ST;
    float v[3];
    #pragma unroll
    for (int c = 0; c < 3; c++) {
        int d = tid + c * 256;
        float add;
        if (p == 0) {
            float s = 0.f;
            #pragma unroll
            for (int t = 0; t < TT; t++)
                s += __half2float(op[((long)((b * TT + t) * NT)) * D + d]);
            add = s * (1.0f / TT);
        } else {
            int q = p - 1;
            int hw = q / TT, t = q % TT;
            add = __half2float(op[((long)((b * TT + t) * NT + 1 + hw)) * D + d]);
        }
        v[c] = x[(long)row * D + d] + add;
        y[(long)row * D + d] = v[c];
    }
    __shared__ float red[256];
    red[tid] = v[0] + v[1] + v[2];
    __syncthreads();
    for (int o = 128; o > 0; o >>= 1) { if (tid < o) red[tid] += red[tid + o]; __syncthreads(); }
    float mean = red[0] * (1.0f / D);
    __syncthreads();
    float d0 = v[0] - mean, d1 = v[1] - mean, d2 = v[2] - mean;
    red[tid] = d0*d0 + d1*d1 + d2*d2;
    __syncthreads();
    for (int o = 128; o > 0; o >>= 1) { if (tid < o) red[tid] += red[tid + o]; __syncthreads(); }
    float rs = rsqrtf(red[0] * (1.0f / D) + 1e-5f);
    __half* yr = xn2h + (long)row * D;
    yr[tid]       = __float2half(d0 * rs * g[tid]       + be[tid]);
    yr[tid + 256] = __float2half(d1 * rs * g[tid + 256] + be[tid + 256]);
    yr[tid + 512] = __float2half(d2 * rs * g[tid + 512] + be[tid + 512]);
}

// ---------------- launcher ----------------
extern "C" void kernel_launch(void* const* d_in, const int* in_sizes, int n_in,
                              void* d_out, int out_size) {
    const float* x    = (const float*)d_in[0];
    const float* Wmq  = (const float*)d_in[1];
    const float* bmq  = (const float*)d_in[2];
    const float* Wmk  = (const float*)d_in[3];
    const float* bmk  = (const float*)d_in[4];
    const float* g1   = (const float*)d_in[5];
    const float* be1  = (const float*)d_in[6];
    const float* Wqkv = (const float*)d_in[7];
    const float* Wpr  = (const float*)d_in[8];
    const float* bpr  = (const float*)d_in[9];
    const float* g2   = (const float*)d_in[10];
    const float* be2  = (const float*)d_in[11];
    const float* Wf1  = (const float*)d_in[12];
    const float* bf1  = (const float*)d_in[13];
    const float* Wf2  = (const float*)d_in[14];
    const float* bf2  = (const float*)d_in[15];

    float* out = (float*)d_out;
    float* y   = out;
    float* lm  = out + YSZ;

    float *bqk;
    __half *xth, *xnh, *qmkh, *qkvh, *oh, *oph, *xn2h, *hh, *wqkh, *wqkvh, *wprh, *wf1h, *wf2h;
    cudaGetSymbolAddress((void**)&xth,  g_xth);
    cudaGetSymbolAddress((void**)&xnh,  g_xnh);
    cudaGetSymbolAddress((void**)&qmkh, g_qmkh);
    cudaGetSymbolAddress((void**)&bqk,  g_bqk);
    cudaGetSymbolAddress((void**)&qkvh, g_qkvh);
    cudaGetSymbolAddress((void**)&oh,   g_oh);
    cudaGetSymbolAddress((void**)&oph,  g_oph);
    cudaGetSymbolAddress((void**)&xn2h, g_xn2h);
    cudaGetSymbolAddress((void**)&hh,   g_hh);
    cudaGetSymbolAddress((void**)&wqkh, g_wqkh);
    cudaGetSymbolAddress((void**)&wqkvh,g_wqkvh);
    cudaGetSymbolAddress((void**)&wprh, g_wprh);
    cudaGetSymbolAddress((void**)&wf1h, g_wf1h);
    cudaGetSymbolAddress((void**)&wf2h, g_wf2h);

    static int smem_set = 0;
    if (!smem_set) {
        cudaFuncSetAttribute(fused_attn, cudaFuncAttributeMaxDynamicSharedMemorySize, SM_ATT);
        cudaFuncSetAttribute(gemm_h16,  cudaFuncAttributeMaxDynamicSharedMemorySize, SMEM_H);
        smem_set = 1;
    }

    int gy  = (MXT + 127) / 128;   // 99
    int gy2 = (MY  + 127) / 128;   // 99

    // 0) weight prep (fp16)
    round_weights<<<(14 * D * D + 255) / 256, 256>>>(Wqkv, Wpr, Wf1, Wf2, Wmq, Wmk, bmq, bmk);

    // 1) gather + LN1 (fp16 outputs)
    gather_ln<<<MXT, 256>>>(x, g1, be1, xth, xnh);

    // 2) fused mask projections [qm|km] (fp16 out)
    gemm_h16<<<dim3((2*D)/128, gy), 256, SMEM_H>>>(xth, wqkh, bqk, nullptr, nullptr, qmkh,
                                                   MXT, 2*D, D, D, D, 2*D, 0, 0, 0, 0 | 16);

    // 3) lm logits (batched fp16) + fused sigmoid w/ forced [0,0]=100
    gemm_h16<<<dim3(2, 2, BT), 256, SMEM_H>>>(qmkh, qmkh + D, nullptr, nullptr, lm, nullptr,
                                              NT, NT, D, 2*D, 2*D, NT,
                                              (long long)NT*2*D, (long long)NT*2*D,
                                              (long long)NT*NT, 3);

    // 4) QKV projection (fp16 out)
    gemm_h16<<<dim3((3*D)/128, gy), 256, SMEM_H>>>(xnh, wqkvh, nullptr, nullptr, nullptr, qkvh,
                                                   MXT, 3*D, D, D, D, 3*D, 0, 0, 0, 0 | 16);

    // 5) fused attention (fp16)
    fused_attn<<<dim3(4, NHD, BT), 256, SM_ATT>>>(qkvh, lm, oh);

    // 6) output projection (fp16 out), scatter + LN2 (fp16 xn2)
    gemm_h16<<<dim3(D/128, gy), 256, SMEM_H>>>(oh, wprh, bpr, nullptr, nullptr, oph,
                                               MXT, D, D, D, D, D, 0, 0, 0, 0 | 16);
    scatter_ln<<<MY, 256>>>(x, oph, g2, be2, y, xn2h);

    // 7) MLP fp16: fc1(+gelu -> fp16 h) -> fc2(+residual into y)
    gemm_h16<<<dim3(DH/128, gy2), 256, SMEM_H>>>(xn2h, wf1h, bf1, nullptr, nullptr, hh,
                                                 MY, DH, D, D, D, DH, 0, 0, 0, 1 | 16);
    gemm_h16<<<dim3(D/128, gy2), 256, SMEM_H>>>(hh, wf2h, bf2, y, y, nullptr,
                                                MY, D, DH, DH, DH, D, 0, 0, 0, 2);
}

// round 17
// speedup vs baseline: 1.1510x; 1.1510x over previous
#include <cuda_runtime.h>
#include <cuda_fp16.h>
#include <math.h>

// ---------------- problem constants ----------------
#define D    768
#define DH   3072
#define BB   8
#define TT   8
#define NT   197
#define BT   64
#define NHD  12
#define HD   64
#define ST   1569
#define MXT  (BT*NT)        // 12608
#define MY   (BB*ST)        // 12552
#define YSZ  (MY*D)
#define LMSZ (BT*NT*NT)

#define GS   4
#define SMEM_H (GS*2*128*40*2)   // 81920 (fp16 stages)

// ---------------- scratch ----------------
__device__ __half g_xth [MXT*D];
__device__ __half g_xnh [MXT*D];
__device__ __half g_qmkh[MXT*2*D];
__device__ float  g_bqk [2*D];
__device__ __half g_qkvh[MXT*3*D];
__device__ __half g_oh  [MXT*D];
__device__ __half g_oph [MXT*D];
__device__ __half g_xn2h[MY*D];
__device__ __half g_hh  [MY*DH];
__device__ __half g_wqkh [2*D*D];
__device__ __half g_wqkvh[3*D*D];
__device__ __half g_wprh [D*D];
__device__ __half g_wf1h [DH*D];
__device__ __half g_wf2h [D*DH];

// ---------------- helpers ----------------
__device__ __forceinline__ void mma16h(float* c, const unsigned* a, const unsigned* b) {
    asm volatile(
        "mma.sync.aligned.m16n8k16.row.col.f32.f16.f16.f32 "
        "{%0,%1,%2,%3}, {%4,%5,%6,%7}, {%8,%9}, {%0,%1,%2,%3};"
        : "+f"(c[0]), "+f"(c[1]), "+f"(c[2]), "+f"(c[3])
        : "r"(a[0]), "r"(a[1]), "r"(a[2]), "r"(a[3]), "r"(b[0]), "r"(b[1]));
}

__device__ __forceinline__ void ldsm_x4(unsigned* r, unsigned addr) {
    asm volatile("ldmatrix.sync.aligned.m8n8.x4.shared.b16 {%0,%1,%2,%3}, [%4];"
        : "=r"(r[0]), "=r"(r[1]), "=r"(r[2]), "=r"(r[3]) : "r"(addr));
}

__device__ __forceinline__ void cpa16(unsigned dst, const void* src, bool p) {
    asm volatile("cp.async.cg.shared.global [%0], [%1], 16, %2;"
        :: "r"(dst), "l"(src), "r"(p ? 16 : 0));
}
#define CP_COMMIT asm volatile("cp.async.commit_group;")
template<int N> __device__ __forceinline__ void cp_wait() {
    asm volatile("cp.async.wait_group %0;" :: "n"(N));
}

// ---------------- merged weight prep (fp16) ----------------
__global__ void round_weights(const float* __restrict__ Wqkv, const float* __restrict__ Wpr,
                              const float* __restrict__ Wf1, const float* __restrict__ Wf2,
                              const float* __restrict__ Wmq, const float* __restrict__ Wmk,
                              const float* __restrict__ bmq, const float* __restrict__ bmk) {
    const int DD = D * D;
    int i = blockIdx.x * blockDim.x + threadIdx.x;
    if (i < 3 * DD)        g_wqkvh[i]          = __float2half(Wqkv[i]);
    else if (i < 4 * DD)   g_wprh[i - 3 * DD]  = __float2half(Wpr[i - 3 * DD]);
    else if (i < 8 * DD)   g_wf1h[i - 4 * DD]  = __float2half(Wf1[i - 4 * DD]);
    else if (i < 12 * DD)  g_wf2h[i - 8 * DD]  = __float2half(Wf2[i - 8 * DD]);
    else if (i < 13 * DD)  g_wqkh[i - 12 * DD] = __float2half(Wmq[i - 12 * DD]);
    else if (i < 14 * DD)  g_wqkh[DD + i - 13 * DD] = __float2half(Wmk[i - 13 * DD]);
    if (i < D) g_bqk[i] = bmq[i];
    else if (i < 2 * D) g_bqk[i] = bmk[i - D];
}

// ---------------- fused gather + LayerNorm1 -> xth, xnh (fp16) ----------------
__global__ void gather_ln(const float* __restrict__ x, const float* __restrict__ g,
                          const float* __restrict__ be,
                          __half* __restrict__ xth, __half* __restrict__ xnh) {
    int row = blockIdx.x;
    int tid = threadIdx.x;
    int n  = row % NT;
    int bt = row / NT;
    int b = bt / TT, t = bt % TT;
    int src = (n == 0) ? (b * ST) : (b * ST + 1 + (n - 1) * TT + t);
    const float* xr = x + (long)src * D;
    float v0 = xr[tid], v1 = xr[tid + 256], v2 = xr[tid + 512];
    __half* xtr = xth + (long)row * D;
    xtr[tid] = __float2half(v0); xtr[tid + 256] = __float2half(v1); xtr[tid + 512] = __float2half(v2);

    __shared__ float red[256];
    red[tid] = v0 + v1 + v2;
    __syncthreads();
    for (int o = 128; o > 0; o >>= 1) { if (tid < o) red[tid] += red[tid + o]; __syncthreads(); }
    float mean = red[0] * (1.0f / D);
    __syncthreads();
    float d0 = v0 - mean, d1 = v1 - mean, d2 = v2 - mean;
    red[tid] = d0*d0 + d1*d1 + d2*d2;
    __syncthreads();
    for (int o = 128; o > 0; o >>= 1) { if (tid < o) red[tid] += red[tid + o]; __syncthreads(); }
    float rs = rsqrtf(red[0] * (1.0f / D) + 1e-5f);
    __half* yr = xnh + (long)row * D;
    yr[tid]       = __float2half(d0 * rs * g[tid]       + be[tid]);
    yr[tid + 256] = __float2half(d1 * rs * g[tid + 256] + be[tid + 256]);
    yr[tid + 512] = __float2half(d2 * rs * g[tid + 512] + be[tid + 512]);
}

// ---------------- fp16 GEMM: m16n8k16, K-tile=32 halves, GS=4 (R15 config) ----------------
// A: MxK f16 (lda), B: NxK f16 (ldb). Batch via blockIdx.z when sC != 0.
// ep low 3 bits: 0=+bias 1=+bias,gelu 2=+bias,+Res 3=sigmoid w/ forced [0,0]=100
// bit4 (16): out fp16 to Ch (else fp32 to C)
__global__ __launch_bounds__(256, 2) void gemm_h16(
    const __half* __restrict__ A, const __half* __restrict__ B,
    const float* __restrict__ bias, const float* __restrict__ Res,
    float* __restrict__ C, __half* __restrict__ Ch,
    int M, int N, int K, int lda, int ldb, int ldc,
    long long sAo, long long sBo, long long sC, int ep)
{
    extern __shared__ __align__(16) float dyn[];

    int tid  = threadIdx.x;
    int warp = tid >> 5, lane = tid & 31;
    int g = lane >> 2, tig = lane & 3;
    int wm = warp >> 2;
    int wn = warp & 3;
    int m0 = blockIdx.y * 128, n0 = blockIdx.x * 128;

    const __half* Ab = A;
    const __half* Bb = B;
    float* Cb = C;
    __half* Chb = Ch;
    if (sC) {
        long long z = blockIdx.z;
        Ab += z * sAo;
        Bb += z * sBo;
        if (C)  Cb  += z * sC;
        if (Ch) Chb += z * sC;
    }

    int lrow = tid >> 1;
    int lch  = (tid & 1) * 2;
    bool aok = (m0 + lrow) < M;
    bool bok = (n0 + lrow) < N;
    const __half* Ap = A == Ab ? A + (long long)(m0 + lrow) * lda + lch * 8
                               : Ab + (long long)(m0 + lrow) * lda + lch * 8;
    const __half* Bp = Bb + (long long)(n0 + lrow) * ldb + lch * 8;

    unsigned smB = (unsigned)__cvta_generic_to_shared(dyn);
    const unsigned STG = 128 * 40 * 2;
    unsigned aSt = smB + lrow * 80 + lch * 16;
    unsigned bSt = smB + GS * STG + lrow * 80 + lch * 16;

    int arow = lane & 15;
    int acolB = (lane >> 4) * 16;
    int brow = (lane & 7) + ((lane & 16) >> 1);
    int bcolB = ((lane >> 3) & 1) * 16;
    unsigned aAddr = smB + (wm * 64 + arow) * 80 + acolB;
    unsigned bAddr = smB + GS * STG + (wn * 32 + brow) * 80 + bcolB;

    float acc[4][4][4];
    #pragma unroll
    for (int mt = 0; mt < 4; mt++)
        #pragma unroll
        for (int nt = 0; nt < 4; nt++)
            #pragma unroll
            for (int i = 0; i < 4; i++) acc[mt][nt][i] = 0.f;

    int nkt = K >> 5;

    #pragma unroll
    for (int s = 0; s < GS - 1; s++) {
        bool has = s < nkt;
        cpa16(aSt + s * STG,      Ap + s * 32,     aok && has);
        cpa16(aSt + s * STG + 16, Ap + s * 32 + 8, aok && has);
        cpa16(bSt + s * STG,      Bp + s * 32,     bok && has);
        cpa16(bSt + s * STG + 16, Bp + s * 32 + 8, bok && has);
        CP_COMMIT;
    }

#define LOADFRAGH(aB, bB, kko) do { \
        ldsm_x4(fa[0], (aB) + 0 * 1280 + (kko)); \
        ldsm_x4(fa[1], (aB) + 1 * 1280 + (kko)); \
        ldsm_x4(fa[2], (aB) + 2 * 1280 + (kko)); \
        ldsm_x4(fa[3], (aB) + 3 * 1280 + (kko)); \
        ldsm_x4(fb2[0], (bB) + 0 * 1280 + (kko)); \
        ldsm_x4(fb2[1], (bB) + 1 * 1280 + (kko)); \
    } while (0)
#define MMAH_ALL do { \
        _Pragma("unroll") \
        for (int mt = 0; mt < 4; mt++) \
            _Pragma("unroll") \
            for (int nt = 0; nt < 4; nt++) { \
                unsigned bb[2] = { fb2[nt >> 1][(nt & 1) * 2], fb2[nt >> 1][(nt & 1) * 2 + 1] }; \
                mma16h(acc[mt][nt], fa[mt], bb); \
            } \
    } while (0)

    for (int kt = 0; kt < nkt; kt++) {
        cp_wait<GS - 2>();
        __syncthreads();
        int cur = kt & (GS - 1);
        unsigned aB = aAddr + cur * STG;
        unsigned bB = bAddr + cur * STG;

        {
            int pf = kt + GS - 1;
            bool has = pf < nkt;
            int ps = pf & (GS - 1);
            cpa16(aSt + ps * STG,      Ap + pf * 32,     aok && has);
            cpa16(aSt + ps * STG + 16, Ap + pf * 32 + 8, aok && has);
            cpa16(bSt + ps * STG,      Bp + pf * 32,     bok && has);
            cpa16(bSt + ps * STG + 16, Bp + pf * 32 + 8, bok && has);
            CP_COMMIT;
        }

        unsigned fa[4][4], fb2[2][4];
        LOADFRAGH(aB, bB, 0);
        MMAH_ALL;
        LOADFRAGH(aB, bB, 32);
        MMAH_ALL;
    }
#undef LOADFRAGH
#undef MMAH_ALL

    int base_ep = ep & 7;
    bool outh = (ep & 16) != 0;
    bool v2ok = (ldc & 1) == 0;

    #pragma unroll
    for (int mt = 0; mt < 4; mt++) {
        int r0 = m0 + wm * 64 + mt * 16 + g;
        #pragma unroll
        for (int nt = 0; nt < 4; nt++) {
            int c0 = n0 + wn * 32 + nt * 8 + tig * 2;
            #pragma unroll
            for (int i = 0; i < 2; i++) {
                int rr = r0 + i * 8;
                if (rr >= M) continue;
                float v[2];
                #pragma unroll
                for (int j = 0; j < 2; j++) {
                    int cc = c0 + j;
                    float t = acc[mt][nt][i * 2 + j];
                    if (base_ep == 3) {
                        if (rr == 0 && cc == 0) t = 100.0f;
                        t = 1.0f / (1.0f + expf(-t));
                    } else {
                        if (bias) t += bias[cc];
                        if (base_ep == 1) t = 0.5f * t * (1.0f + erff(t * 0.7071067811865476f));
                        else if (base_ep == 2) t += Res[(long long)rr * ldc + cc];
                    }
                    v[j] = t;
                }
                if (outh) {
                    __half2 p;
                    p.x = __float2half(v[0]);
                    p.y = __float2half(v[1]);
                    *(__half2*)&Chb[(long long)rr * ldc + c0] = p;
                } else if (v2ok && c0 + 1 < N) {
                    *(float2*)&Cb[(long long)rr * ldc + c0] = make_float2(v[0], v[1]);
                } else {
                    if (c0 < N)     Cb[(long long)rr * ldc + c0] = v[0];
                    if (c0 + 1 < N) Cb[(long long)rr * ldc + c0 + 1] = v[1];
                }
            }
        }
    }
}

// ---------------- fused attention, fp16 MMAs + fp16 score buffer (2 CTA/SM) ----------------
#define SKH 72
#define SPH 210
#define OQ  0
#define OK_ (OQ + 64*SKH)
#define OV  (OK_ + 200*SKH)
#define OP_ (OV + 64*SPH)
#define SM_ATT ((OP_ + 64*SPH)*2)

__global__ __launch_bounds__(256, 2) void fused_attn(
    const __half* __restrict__ qkv, const float* __restrict__ lm, __half* __restrict__ o)
{
    extern __shared__ char smc[];
    __half* Qs = (__half*)smc + OQ;
    __half* Ks = (__half*)smc + OK_;
    __half* Vt = (__half*)smc + OV;
    __half* Ph = (__half*)smc + OP_;

    int tid = threadIdx.x;
    int w = tid >> 5, lane = tid & 31;
    int g = lane >> 2, tig = lane & 3;
    int qi = blockIdx.x, h = blockIdx.y, bt = blockIdx.z;
    int q0 = qi * 64;
    const __half* base = qkv + (long)bt * NT * 3 * D + h * HD;

    {
        int r = tid >> 2;
        int c = (tid & 3) * 16;
        int q = q0 + r;
        if (q < NT) {
            const uint4* p = (const uint4*)(base + (long)q * 3 * D + c);
            *(uint4*)&Qs[r * SKH + c]     = p[0];
            *(uint4*)&Qs[r * SKH + c + 8] = p[1];
        } else {
            #pragma unroll
            for (int j = 0; j < 16; j++) Qs[r * SKH + c + j] = __float2half(0.f);
        }
    }
    {
        int c = (tid & 3) * 16;
        for (int r = tid >> 2; r < NT; r += 64) {
            const uint4* p = (const uint4*)(base + (long)r * 3 * D + D + c);
            *(uint4*)&Ks[r * SKH + c]     = p[0];
            *(uint4*)&Ks[r * SKH + c + 8] = p[1];
        }
        for (int i = tid; i < 3 * 64; i += 256)
            Ks[(197 + i / 64) * SKH + (i % 64)] = __float2half(0.f);
    }
    {
        int c4 = (tid & 15) * 4;
        for (int m = tid >> 4; m < NT; m += 16) {
            const __half* vp = base + (long)m * 3 * D + 2 * D + c4;
            __half2 va = *(const __half2*)vp;
            __half2 vb = *(const __half2*)(vp + 2);
            Vt[(c4 + 0) * SPH + m] = va.x;
            Vt[(c4 + 1) * SPH + m] = va.y;
            Vt[(c4 + 2) * SPH + m] = vb.x;
            Vt[(c4 + 3) * SPH + m] = vb.y;
        }
        for (int i = tid; i < 64 * 13; i += 256)
            Vt[(i / 13) * SPH + 197 + (i % 13)] = __float2half(0.f);
    }
    __syncthreads();

    {
        int wm = w & 3;
        int wn = w >> 2;
        int nt0 = wn ? 13 : 0, nt1 = wn ? 25 : 13;
        int ra0 = (wm * 16 + g) * SKH;
        for (int nt = nt0; nt < nt1; nt++) {
            float c[4] = {0.f, 0.f, 0.f, 0.f};
            int rb0 = (nt * 8 + g) * SKH;
            #pragma unroll
            for (int kk = 0; kk < 64; kk += 16) {
                unsigned a[4], b[2];
                a[0] = *(const unsigned*)&Qs[ra0 + kk + 2 * tig];
                a[1] = *(const unsigned*)&Qs[ra0 + 8 * SKH + kk + 2 * tig];
                a[2] = *(const unsigned*)&Qs[ra0 + kk + 2 * tig + 8];
                a[3] = *(const unsigned*)&Qs[ra0 + 8 * SKH + kk + 2 * tig + 8];
                b[0] = *(const unsigned*)&Ks[rb0 + kk + 2 * tig];
                b[1] = *(const unsigned*)&Ks[rb0 + kk + 2 * tig + 8];
                mma16h(c, a, b);
            }
            int rm = wm * 16 + g, cn = nt * 8 + tig * 2;
            __half2 p0, p1;
            p0.x = __float2half(c[0]); p0.y = __float2half(c[1]);
            p1.x = __float2half(c[2]); p1.y = __float2half(c[3]);
            *(__half2*)&Ph[rm * SPH + cn]       = p0;
            *(__half2*)&Ph[(rm + 8) * SPH + cn] = p1;
        }
    }
    __syncthreads();

    {
        for (int rr = 0; rr < 8; rr++) {
            int r = (w << 3) + rr;
            int q = q0 + r;
            if (q < NT) {
                const float* lmr = lm + ((long)bt * NT + q) * NT;
                float mx = -1e30f;
                for (int k = lane; k < NT; k += 32) mx = fmaxf(mx, __half2float(Ph[r * SPH + k]));
                #pragma unroll
                for (int s = 16; s > 0; s >>= 1) mx = fmaxf(mx, __shfl_xor_sync(0xffffffffu, mx, s));
                float sum = 0.f;
                float ev[7];
                int cnt = 0;
                for (int k = lane; k < NT; k += 32) {
                    float e = expf(0.125f * (__half2float(Ph[r * SPH + k]) - mx));
                    ev[cnt++] = e;
                    sum += e;
                }
                #pragma unroll
                for (int s = 16; s > 0; s >>= 1) sum += __shfl_xor_sync(0xffffffffu, sum, s);
                float inv = 1.0f / sum;
                cnt = 0;
                for (int k = lane; k < SPH; k += 32) {
                    float p = (k < NT) ? (ev[cnt++] * inv * lmr[k]) : 0.f;
                    Ph[r * SPH + k] = __float2half(p);
                }
            } else {
                for (int k = lane; k < SPH; k += 32) Ph[r * SPH + k] = __float2half(0.f);
            }
        }
    }
    __syncthreads();

    {
        int wmA = w >> 1;
        int wnA = w & 1;
        float acc[4][4];
        #pragma unroll
        for (int nt = 0; nt < 4; nt++)
            #pragma unroll
            for (int i = 0; i < 4; i++) acc[nt][i] = 0.f;

        int ra0 = (wmA * 16 + g) * SPH;
        for (int kk = 0; kk < 208; kk += 16) {
            unsigned a[4], b[4][2];
            a[0] = *(const unsigned*)&Ph[ra0 + kk + 2 * tig];
            a[1] = *(const unsigned*)&Ph[ra0 + 8 * SPH + kk + 2 * tig];
            a[2] = *(const unsigned*)&Ph[ra0 + kk + 2 * tig + 8];
            a[3] = *(const unsigned*)&Ph[ra0 + 8 * SPH + kk + 2 * tig + 8];
            #pragma unroll
            for (int nt = 0; nt < 4; nt++) {
                int rb0 = (wnA * 32 + nt * 8 + g) * SPH;
                b[nt][0] = *(const unsigned*)&Vt[rb0 + kk + 2 * tig];
                b[nt][1] = *(const unsigned*)&Vt[rb0 + kk + 2 * tig + 8];
            }
            #pragma unroll
            for (int nt = 0; nt < 4; nt++) mma16h(acc[nt], a, b[nt]);
        }

        #pragma unroll
        for (int nt = 0; nt < 4; nt++) {
            int cn = wnA * 32 + nt * 8 + tig * 2;
            #pragma unroll
            for (int i = 0; i < 2; i++) {
                int q = q0 + wmA * 16 + g + i * 8;
                if (q >= NT) continue;
                __half* op = o + ((long)bt * NT + q) * D + h * HD + cn;
                __half2 p;
                p.x = __float2half(acc[nt][i * 2]);
                p.y = __float2half(acc[nt][i * 2 + 1]);
                *(__half2*)op = p;
            }
        }
    }
}

// ---------------- fused scatter(+residual, fp16 op) + LayerNorm2 -> y (fp32), xn2h ----------------
__global__ void scatter_ln(const float* __restrict__ x, const __half* __restrict__ op,
                           const float* __restrict__ g, const float* __restrict__ be,
                           float* __restrict__ y, __half* __restrict__ xn2h) {
    int row = blockIdx.x;
    int tid = threadIdx.x;
    int p = row % ST;
    int b = row / ST;
    float v[3];
    #pragma unroll
    for (int c = 0; c < 3; c++) {
        int d = tid + c * 256;
        float add;
        if (p == 0) {
            float s = 0.f;
            #pragma unroll
            for (int t = 0; t < TT; t++)
                s += __half2float(op[((long)((b * TT + t) * NT)) * D + d]);
            add = s * (1.0f / TT);
        } else {
            int q = p - 1;
            int hw = q / TT, t = q % TT;
            add = __half2float(op[((long)((b * TT + t) * NT + 1 + hw)) * D + d]);
        }
        v[c] = x[(long)row * D + d] + add;
        y[(long)row * D + d] = v[c];
    }
    __shared__ float red[256];
    red[tid] = v[0] + v[1] + v[2];
    __syncthreads();
    for (int o = 128; o > 0; o >>= 1) { if (tid < o) red[tid] += red[tid + o]; __syncthreads(); }
    float mean = red[0] * (1.0f / D);
    __syncthreads();
    float d0 = v[0] - mean, d1 = v[1] - mean, d2 = v[2] - mean;
    red[tid] = d0*d0 + d1*d1 + d2*d2;
    __syncthreads();
    for (int o = 128; o > 0; o >>= 1) { if (tid < o) red[tid] += red[tid + o]; __syncthreads(); }
    float rs = rsqrtf(red[0] * (1.0f / D) + 1e-5f);
    __half* yr = xn2h + (long)row * D;
    yr[tid]       = __float2half(d0 * rs * g[tid]       + be[tid]);
    yr[tid + 256] = __float2half(d1 * rs * g[tid + 256] + be[tid + 256]);
    yr[tid + 512] = __float2half(d2 * rs * g[tid + 512] + be[tid + 512]);
}

// ---------------- launcher ----------------
extern "C" void kernel_launch(void* const* d_in, const int* in_sizes, int n_in,
                              void* d_out, int out_size) {
    const float* x    = (const float*)d_in[0];
    const float* Wmq  = (const float*)d_in[1];
    const float* bmq  = (const float*)d_in[2];
    const float* Wmk  = (const float*)d_in[3];
    const float* bmk  = (const float*)d_in[4];
    const float* g1   = (const float*)d_in[5];
    const float* be1  = (const float*)d_in[6];
    const float* Wqkv = (const float*)d_in[7];
    const float* Wpr  = (const float*)d_in[8];
    const float* bpr  = (const float*)d_in[9];
    const float* g2   = (const float*)d_in[10];
    const float* be2  = (const float*)d_in[11];
    const float* Wf1  = (const float*)d_in[12];
    const float* bf1  = (const float*)d_in[13];
    const float* Wf2  = (const float*)d_in[14];
    const float* bf2  = (const float*)d_in[15];

    float* out = (float*)d_out;
    float* y   = out;
    float* lm  = out + YSZ;

    float *bqk;
    __half *xth, *xnh, *qmkh, *qkvh, *oh, *oph, *xn2h, *hh, *wqkh, *wqkvh, *wprh, *wf1h, *wf2h;
    cudaGetSymbolAddress((void**)&xth,  g_xth);
    cudaGetSymbolAddress((void**)&xnh,  g_xnh);
    cudaGetSymbolAddress((void**)&qmkh, g_qmkh);
    cudaGetSymbolAddress((void**)&bqk,  g_bqk);
    cudaGetSymbolAddress((void**)&qkvh, g_qkvh);
    cudaGetSymbolAddress((void**)&oh,   g_oh);
    cudaGetSymbolAddress((void**)&oph,  g_oph);
    cudaGetSymbolAddress((void**)&xn2h, g_xn2h);
    cudaGetSymbolAddress((void**)&hh,   g_hh);
    cudaGetSymbolAddress((void**)&wqkh, g_wqkh);
    cudaGetSymbolAddress((void**)&wqkvh,g_wqkvh);
    cudaGetSymbolAddress((void**)&wprh, g_wprh);
    cudaGetSymbolAddress((void**)&wf1h, g_wf1h);
    cudaGetSymbolAddress((void**)&wf2h, g_wf2h);

    static int smem_set = 0;
    if (!smem_set) {
        cudaFuncSetAttribute(fused_attn, cudaFuncAttributeMaxDynamicSharedMemorySize, SM_ATT);
        cudaFuncSetAttribute(gemm_h16,  cudaFuncAttributeMaxDynamicSharedMemorySize, SMEM_H);
        smem_set = 1;
    }

    int gy  = (MXT + 127) / 128;   // 99
    int gy2 = (MY  + 127) / 128;   // 99

    // 0) weight prep (fp16)
    round_weights<<<(14 * D * D + 255) / 256, 256>>>(Wqkv, Wpr, Wf1, Wf2, Wmq, Wmk, bmq, bmk);

    // 1) gather + LN1 (fp16 outputs)
    gather_ln<<<MXT, 256>>>(x, g1, be1, xth, xnh);

    // 2) fused mask projections [qm|km] (fp16 out)
    gemm_h16<<<dim3((2*D)/128, gy), 256, SMEM_H>>>(xth, wqkh, bqk, nullptr, nullptr, qmkh,
                                                   MXT, 2*D, D, D, D, 2*D, 0, 0, 0, 0 | 16);

    // 3) lm logits (batched fp16) + fused sigmoid w/ forced [0,0]=100
    gemm_h16<<<dim3(2, 2, BT), 256, SMEM_H>>>(qmkh, qmkh + D, nullptr, nullptr, lm, nullptr,
                                              NT, NT, D, 2*D, 2*D, NT,
                                              (long long)NT*2*D, (long long)NT*2*D,
                                              (long long)NT*NT, 3);

    // 4) QKV projection (fp16 out)
    gemm_h16<<<dim3((3*D)/128, gy), 256, SMEM_H>>>(xnh, wqkvh, nullptr, nullptr, nullptr, qkvh,
                                                   MXT, 3*D, D, D, D, 3*D, 0, 0, 0, 0 | 16);

    // 5) fused attention (fp16)
    fused_attn<<<dim3(4, NHD, BT), 256, SM_ATT>>>(qkvh, lm, oh);

    // 6) output projection (fp16 out), scatter + LN2 (fp16 xn2)
    gemm_h16<<<dim3(D/128, gy), 256, SMEM_H>>>(oh, wprh, bpr, nullptr, nullptr, oph,
                                               MXT, D, D, D, D, D, 0, 0, 0, 0 | 16);
    scatter_ln<<<MY, 256>>>(x, oph, g2, be2, y, xn2h);

    // 7) MLP fp16: fc1(+gelu -> fp16 h) -> fc2(+residual into y)
    gemm_h16<<<dim3(DH/128, gy2), 256, SMEM_H>>>(xn2h, wf1h, bf1, nullptr, nullptr, hh,
                                                 MY, DH, D, D, D, DH, 0, 0, 0, 1 | 16);
    gemm_h16<<<dim3(D/128, gy2), 256, SMEM_H>>>(hh, wf2h, bf2, y, y, nullptr,
                                                MY, D, DH, DH, DH, D, 0, 0, 0, 2);
}